// round 11
// baseline (speedup 1.0000x reference)
#include <cuda_runtime.h>
#include <math.h>

// ============================================================================
// Compile-time real Clebsch-Gordan tensor (exact replica of reference _real_cg)
// ============================================================================
#define DH __host__ __device__

namespace cgct {

DH constexpr double fact(int n) {
    double r = 1.0;
    for (int i = 2; i <= n; ++i) r *= (double)i;
    return r;
}

DH constexpr double csqrt(double x) {
    if (x <= 0.0) return 0.0;
    double g = x < 1.0 ? 1.0 : x;
    for (int i = 0; i < 200; ++i) g = 0.5 * (g + x / g);
    return g;
}

DH constexpr int iabs(int x) { return x < 0 ? -x : x; }
DH constexpr double m1p(int k) { return (k % 2 != 0) ? -1.0 : 1.0; }

DH constexpr double clebsch(int j1, int m1, int j2, int m2, int j3, int m3) {
    if (m1 + m2 != m3) return 0.0;
    if (j3 < iabs(j1 - j2) || j3 > j1 + j2) return 0.0;
    double pre = csqrt((2.0 * j3 + 1.0) * fact(j1 + j2 - j3) * fact(j1 - j2 + j3) *
                       fact(-j1 + j2 + j3) / fact(j1 + j2 + j3 + 1));
    pre = pre * csqrt(fact(j3 + m3) * fact(j3 - m3) * fact(j1 - m1) *
                      fact(j1 + m1) * fact(j2 - m2) * fact(j2 + m2));
    double s = 0.0;
    for (int k = 0; k <= j1 + j2 + j3; ++k) {
        int d0 = k, d1 = j1 + j2 - j3 - k, d2 = j1 - m1 - k;
        int d3 = j2 + m2 - k, d4 = j3 - j2 + m1 + k, d5 = j3 - j1 - m2 + k;
        if (d0 < 0 || d1 < 0 || d2 < 0 || d3 < 0 || d4 < 0 || d5 < 0) continue;
        s += m1p(k) / (fact(d0) * fact(d1) * fact(d2) * fact(d3) * fact(d4) * fact(d5));
    }
    return pre * s;
}

struct C2 { double re, im; };
DH constexpr C2 cmul(C2 a, C2 b) { return {a.re * b.re - a.im * b.im, a.re * b.im + a.im * b.re}; }
DH constexpr C2 cconj(C2 a) { return {a.re, -a.im}; }

DH constexpr C2 Uel(int l, int i, int k) {
    double s2 = 1.0 / csqrt(2.0);
    int m = i - l;
    if (m == 0) return (k == l) ? C2{1.0, 0.0} : C2{0.0, 0.0};
    if (m > 0) {
        if (k == l + m) return C2{m1p(m) * s2, 0.0};
        if (k == l - m) return C2{s2, 0.0};
        return C2{0.0, 0.0};
    }
    if (k == l + m) return C2{0.0, s2};
    if (k == l - m) return C2{0.0, -m1p(m) * s2};
    return C2{0.0, 0.0};
}

DH constexpr int l_of(int I) { return I == 0 ? 0 : (I < 4 ? 1 : 2); }
DH constexpr int o_of(int l) { return l == 0 ? 0 : (l == 1 ? 1 : 4); }

DH constexpr double CGC(int I, int J, int K) {
    int l1 = l_of(I), l2 = l_of(J), l3 = l_of(K);
    if (l3 < iabs(l1 - l2) || l3 > l1 + l2) return 0.0;
    int i = I - o_of(l1), j = J - o_of(l2), kk = K - o_of(l3);
    double re = 0.0, im = 0.0;
    for (int a = 0; a < 2 * l1 + 1; ++a) {
        for (int b = 0; b < 2 * l2 + 1; ++b) {
            int m1 = a - l1, m2 = b - l2, m3 = m1 + m2;
            if (m3 < -l3 || m3 > l3) continue;
            int c = m3 + l3;
            double v = clebsch(l1, m1, l2, m2, l3, m3);
            if (v == 0.0) continue;
            C2 t = cmul(cmul(Uel(l1, i, a), Uel(l2, j, b)), cconj(Uel(l3, kk, c)));
            re += t.re * v;
            im += t.im * v;
        }
    }
    return re + im;
}

DH constexpr bool anyNZ(int I, int J, int o3, int nl3) {
    for (int c = 0; c < nl3; ++c)
        if (CGC(I, J, o3 + c) != 0.0) return true;
    return false;
}

} // namespace cgct

// ============================================================================
// Chebyshev U monomial coefficients: sin((k+1)a) = U_k(cos a) * sin(a)
// ============================================================================
struct ChebT {
    double T[8][8];
    constexpr ChebT() : T{} {
        T[0][0] = 1.0;
        T[1][1] = 2.0;
        for (int k = 2; k < 8; ++k)
            for (int j = 0; j < 8; ++j)
                T[k][j] = 2.0 * (j > 0 ? T[k - 1][j - 1] : 0.0) - T[k - 2][j];
    }
};
constexpr ChebT CT{};

// ============================================================================
// static-for
// ============================================================================
template <int I> struct IC { static constexpr int v = I; };
template <int N, class F>
__device__ __forceinline__ void sfor(F&& f) {
    if constexpr (N > 0) {
        sfor<N - 1>(f);
        f(IC<N - 1>{});
    }
}

template <int I>
__device__ __forceinline__ float getf4(const float4& v) {
    if constexpr (I == 0) return v.x;
    else if constexpr (I == 1) return v.y;
    else if constexpr (I == 2) return v.z;
    else return v.w;
}

// ============================================================================
// packed f32x2 helpers
// ============================================================================
using u64 = unsigned long long;

__device__ __forceinline__ u64 pk2(float lo, float hi) {
    u64 r;
    asm("mov.b64 %0, {%1, %2};" : "=l"(r) : "f"(lo), "f"(hi));
    return r;
}
__device__ __forceinline__ u64 pk1(float v) { return pk2(v, v); }
__device__ __forceinline__ void upk(u64 v, float& lo, float& hi) {
    asm("mov.b64 {%0, %1}, %2;" : "=f"(lo), "=f"(hi) : "l"(v));
}
__device__ __forceinline__ u64 f2mul(u64 a, u64 b) {
    u64 d;
    asm("mul.rn.f32x2 %0, %1, %2;" : "=l"(d) : "l"(a), "l"(b));
    return d;
}
__device__ __forceinline__ u64 f2fma(u64 a, u64 b, u64 c) {
    u64 d;
    asm("fma.rn.f32x2 %0, %1, %2, %3;" : "=l"(d) : "l"(a), "l"(b), "l"(c));
    return d;
}

// ============================================================================
// Problem constants & scratch
// ============================================================================
constexpr int NE = 320000;
constexpr int NN = 10000;
constexpr int NN_MAX = 10240;
constexpr int FT = 32;

__device__ float4 g_geom[NE * 3];
__device__ int2   g_sd[NE];         // (src, dst), sorted by dst
__device__ int    g_cnt[NN_MAX];    // zero at load; re-zeroed by scan each run
__device__ int    g_off[NN_MAX];
__device__ float  g_x[NN * 9 * FT];
__device__ float  g_y[NN * 9 * FT]; // zero at load; re-zeroed by node0/node1
__device__ float  g_y2[NN * FT];    // zero at load; re-zeroed by node1

// Path lists
template <int IT> struct PathsT;
template <> struct PathsT<0> {
    static constexpr int L[3][3] = {{0,0,0},{0,1,1},{0,2,2}};
};
template <> struct PathsT<1> {
    static constexpr int L[15][3] = {
        {0,0,0},{0,1,1},{0,2,2},
        {1,0,1},{1,1,0},{1,1,1},{1,1,2},{1,2,1},{1,2,2},
        {2,0,2},{2,1,1},{2,1,2},{2,2,0},{2,2,1},{2,2,2}};
};
template <> struct PathsT<2> {
    static constexpr int L[3][3] = {{0,0,0},{1,1,0},{2,2,0}};
};

// ============================================================================
// Launch 1: histogram (dst counts) + init node features
// ============================================================================
__global__ void hist_initx_kernel(const int* __restrict__ nbr,
                                  const int* __restrict__ Z,
                                  const float* __restrict__ embed,
                                  int E, int N) {
    int i = blockIdx.x * blockDim.x + threadIdx.x;
    if (i < E) atomicAdd(&g_cnt[nbr[i]], 1);
    if (i < N * FT) {
        int n = i >> 5, f = i & 31;
        g_x[(n * 9) * FT + f] = embed[Z[n] * FT + f];
    }
}

// ============================================================================
// Launch 2: exclusive scan of counts -> offsets; re-zero counts for next run
// ============================================================================
__global__ void scan_kernel(int N) {
    __shared__ int ps[1024];
    int tid = threadIdx.x;
    const int PER = 10;
    int base = tid * PER;
    int loc[PER];
    int s = 0;
#pragma unroll
    for (int i = 0; i < PER; ++i) {
        int idx = base + i;
        int v = 0;
        if (idx < N) {
            v = g_cnt[idx];
            g_cnt[idx] = 0;
        }
        loc[i] = s;
        s += v;
    }
    ps[tid] = s;
    __syncthreads();
    for (int off = 1; off < 1024; off <<= 1) {
        int v = (tid >= off) ? ps[tid - off] : 0;
        __syncthreads();
        ps[tid] += v;
        __syncthreads();
    }
    int pre = (tid > 0) ? ps[tid - 1] : 0;
#pragma unroll
    for (int i = 0; i < PER; ++i) {
        int idx = base + i;
        if (idx < N) g_off[idx] = pre + loc[i];
    }
}

// ============================================================================
// Launch 3: scatter edges into dst-sorted order + compute geometry
// ============================================================================
__global__ void scatter_geom_kernel(const int* __restrict__ nbr,
                                    const float* __restrict__ dr, int E) {
    int e = blockIdx.x * blockDim.x + threadIdx.x;
    if (e >= E) return;
    int d = nbr[e];
    int src = nbr[E + e];
    int pos = atomicAdd(&g_off[d], 1);
    g_sd[pos] = make_int2(src, d);

    float dx = dr[e * 3 + 0], dy = dr[e * 3 + 1], dz = dr[e * 3 + 2];
    float r2 = dx * dx + dy * dy + dz * dz + 1e-12f;
    float r = sqrtf(r2);
    float inv = 1.0f / r;
    float ux = dx * inv, uy = dy * inv, uz = dz * inv;

    float t = r * (1.0f / 6.0f);
    t = fminf(fmaxf(t, 0.0f), 1.0f - 1e-6f);
    float cut = (r < 6.0f) ? expf(1.0f - 1.0f / (1.0f - t * t)) : 0.0f;
    float cm = cut * ((d != src) ? 1.0f : 0.0f);

    const float pre = 0.5773502691896258f;   // sqrt(2/6)
    float arg = 0.5235987755982988f * r;     // pi*r/6
    float s1, c1;
    sincosf(arg, &s1, &c1);
    float ss1 = pre * inv * cm * s1;

    const float c0 = 0.28209479177387814f, c1y = 0.4886025119029199f;
    const float c2a = 1.0925484305920792f, c2b = 0.31539156525252005f,
                c2c = 0.5462742152960396f;
    float4* gg = &g_geom[pos * 3];
    gg[0] = make_float4(c0 * ss1, c1y * uy * ss1, c1y * uz * ss1, c1y * ux * ss1);
    gg[1] = make_float4(c2a * ux * uy * ss1, c2a * uy * uz * ss1,
                        c2b * (3.0f * uz * uz - 1.0f) * ss1, c2a * ux * uz * ss1);
    gg[2] = make_float4(c2c * (ux * ux - uy * uy) * ss1, c1, 0.0f, 0.0f);
}

// ============================================================================
// Geometry loader: only Y[YA..YB) plus cos(arg)
// ============================================================================
template <int YA, int YB>
__device__ __forceinline__ void load_geo(int e, float* y, float& c) {
    const float4* gg = &g_geom[e * 3];
    float4 A, B;
    if constexpr (YA < 4) A = gg[0];
    if constexpr (YB > 4 && YA < 8) B = gg[1];
    float2 C2v = *(const float2*)&gg[2];   // (Y8, cos)
    sfor<YB - YA>([&](auto II) {
        constexpr int ii = decltype(II)::v;
        constexpr int i = ii + YA;
        if constexpr (i < 4) y[ii] = getf4<i>(A);
        else if constexpr (i < 8) y[ii] = getf4<i - 4>(B);
        else y[ii] = C2v.x;
    });
    c = C2v.y;
}

// ============================================================================
// flush helper
// ============================================================================
template <int IT, int OC0, int NOC>
__device__ __forceinline__ void tp_flush(u64 (&out)[NOC], int d, int hl) {
#pragma unroll
    for (int c = 0; c < NOC; ++c) {
        float lo, hi;
        upk(out[c], lo, hi);
        float2* addr;
        if constexpr (IT == 2)
            addr = (float2*)&g_y2[d * FT + 2 * hl];
        else
            addr = (float2*)&g_y[(d * 9 + OC0 + c) * FT + 2 * hl];
        atomicAdd(addr, make_float2(lo, hi));
        out[c] = 0;
    }
}

// ============================================================================
// Single-edge compute: Horner radial weight + CG contraction into out.
// ============================================================================
template <int IT, int P0, int P1, int XA, int XB, int OC0, int OC1, int YA, int YB>
__device__ __forceinline__ void tp_compute(
    const u64 (&Vr)[(P1 - P0) * 8],
    const u64 (&xs)[XB - XA],
    const float (&y)[YB - YA], float cv,
    u64 (&out)[OC1 - OC0])
{
    using PT = PathsT<IT>;
    constexpr int NPL = P1 - P0;
    u64 cp = pk1(cv);
    sfor<NPL>([&](auto PI) {
        constexpr int pp = decltype(PI)::v;
        constexpr int p = P0 + pp;
        constexpr int l1 = PT::L[p][0], l2 = PT::L[p][1], l3 = PT::L[p][2];
        constexpr int o1 = cgct::o_of(l1), o2 = cgct::o_of(l2), o3 = cgct::o_of(l3);

        u64 w = Vr[pp * 8 + 7];
#pragma unroll
        for (int j = 6; j >= 0; --j) w = f2fma(w, cp, Vr[pp * 8 + j]);

        constexpr bool wInY = (2 * l2 + 1) < (2 * l1 + 1);
        if constexpr (wInY) {
            u64 yw[2 * l2 + 1];
            sfor<2 * l2 + 1>([&](auto BI) {
                constexpr int b = decltype(BI)::v;
                yw[b] = f2mul(pk1(y[o2 + b - YA]), w);
            });
            sfor<2 * l1 + 1>([&](auto AI) {
                constexpr int a = decltype(AI)::v;
                sfor<2 * l2 + 1>([&](auto BI) {
                    constexpr int b = decltype(BI)::v;
                    if constexpr (cgct::anyNZ(o1 + a, o2 + b, o3, 2 * l3 + 1)) {
                        u64 xy = f2mul(xs[o1 + a - XA], yw[b]);
                        sfor<2 * l3 + 1>([&](auto CI) {
                            constexpr int c = decltype(CI)::v;
                            constexpr double cgv = cgct::CGC(o1 + a, o2 + b, o3 + c);
                            if constexpr (cgv != 0.0) {
                                constexpr int oc = ((IT == 2) ? 0 : (o3 + c)) - OC0;
                                out[oc] = f2fma(pk1((float)cgv), xy, out[oc]);
                            }
                        });
                    }
                });
            });
        } else {
            sfor<2 * l1 + 1>([&](auto AI) {
                constexpr int a = decltype(AI)::v;
                u64 xa = f2mul(xs[o1 + a - XA], w);
                sfor<2 * l2 + 1>([&](auto BI) {
                    constexpr int b = decltype(BI)::v;
                    if constexpr (cgct::anyNZ(o1 + a, o2 + b, o3, 2 * l3 + 1)) {
                        u64 xy = f2mul(xa, pk1(y[o2 + b - YA]));
                        sfor<2 * l3 + 1>([&](auto CI) {
                            constexpr int c = decltype(CI)::v;
                            constexpr double cgv = cgct::CGC(o1 + a, o2 + b, o3 + c);
                            if constexpr (cgv != 0.0) {
                                constexpr int oc = ((IT == 2) ? 0 : (o3 + c)) - OC0;
                                out[oc] = f2fma(pk1((float)cgv), xy, out[oc]);
                            }
                        });
                    }
                });
            });
        }
    });
}

// ============================================================================
// TP body: warp-half (16 lanes) owns a contiguous dst-sorted edge range.
// PAIR processing: two edges per iteration; when both share a dst (common
// case, mean run length ~32) their compute trees form one straight-line
// block -> 2x instruction-level parallelism on the dependency chains.
// ============================================================================
template <int IT, int P0, int P1, int XA, int XB, int OC0, int OC1, int YA, int YB>
__device__ __forceinline__ void tp_body(const float* __restrict__ W, int E,
                                        int halfid, int nhalves) {
    constexpr int NPL = P1 - P0;
    constexpr int NX = XB - XA;
    constexpr int NOC = OC1 - OC0;
    constexpr int NY = YB - YA;

    int lane = threadIdx.x & 31;
    int hl = lane & 15;

    // load raw radial weights, transform to monomial (Chebyshev-U) basis
    u64 Vr[NPL * 8];
    {
        u64 Wr[NPL * 8];
#pragma unroll
        for (int i = 0; i < NPL * 8; ++i)
            Wr[i] = *(const u64*)(W + (P0 * 8 + i) * FT + 2 * hl);
        sfor<NPL>([&](auto PI) {
            constexpr int pp = decltype(PI)::v;
            sfor<8>([&](auto JI) {
                constexpr int j = decltype(JI)::v;
                u64 acc = 0;
                sfor<8>([&](auto KI) {
                    constexpr int k = decltype(KI)::v;
                    constexpr double tkj = CT.T[k][j];
                    if constexpr (tkj != 0.0)
                        acc = f2fma(pk1((float)tkj), Wr[pp * 8 + k], acc);
                });
                Vr[pp * 8 + j] = acc;
            });
        });
    }

    int eph = (E + nhalves - 1) / nhalves;
    int start = halfid * eph;
    int end = start + eph;
    if (end > E) end = E;
    if (start >= end) return;

    u64 out[NOC];
#pragma unroll
    for (int c = 0; c < NOC; ++c) out[c] = 0;
    int dprev = -1;

    int last = end - 1;
    int e = start;
    int2 sdA = g_sd[e];
    int2 sdB = g_sd[(e + 1 <= last) ? e + 1 : last];

#pragma unroll 1
    for (; e + 1 < end; e += 2) {
        // prefetch sd for the next pair
        int2 sdA2 = g_sd[(e + 2 <= last) ? e + 2 : last];
        int2 sdB2 = g_sd[(e + 3 <= last) ? e + 3 : last];

        // issue all loads for this pair up front (high MLP)
        u64 xsA[NX], xsB[NX];
#pragma unroll
        for (int a = 0; a < NX; ++a) {
            xsA[a] = *(const u64*)(g_x + ((sdA.x * 9 + XA + a) * FT) + 2 * hl);
            xsB[a] = *(const u64*)(g_x + ((sdB.x * 9 + XA + a) * FT) + 2 * hl);
        }
        float yA[NY], yB[NY];
        float cA, cB;
        load_geo<YA, YB>(e, yA, cA);
        load_geo<YA, YB>(e + 1, yB, cB);

        if (sdA.y != dprev) {
            if (dprev >= 0) tp_flush<IT, OC0, NOC>(out, dprev, hl);
            dprev = sdA.y;
        }

        if (sdB.y == sdA.y) {
            // fast path: one straight-line block, two independent trees
            tp_compute<IT, P0, P1, XA, XB, OC0, OC1, YA, YB>(Vr, xsA, yA, cA, out);
            tp_compute<IT, P0, P1, XA, XB, OC0, OC1, YA, YB>(Vr, xsB, yB, cB, out);
        } else {
            // dst boundary inside the pair (rare)
            tp_compute<IT, P0, P1, XA, XB, OC0, OC1, YA, YB>(Vr, xsA, yA, cA, out);
            tp_flush<IT, OC0, NOC>(out, dprev, hl);
            dprev = sdB.y;
            tp_compute<IT, P0, P1, XA, XB, OC0, OC1, YA, YB>(Vr, xsB, yB, cB, out);
        }

        sdA = sdA2;
        sdB = sdB2;
    }

    if (e < end) {   // odd tail (sdA == g_sd[e] here)
        u64 xsA[NX];
#pragma unroll
        for (int a = 0; a < NX; ++a)
            xsA[a] = *(const u64*)(g_x + ((sdA.x * 9 + XA + a) * FT) + 2 * hl);
        float yA[NY];
        float cA;
        load_geo<YA, YB>(e, yA, cA);
        if (sdA.y != dprev) {
            if (dprev >= 0) tp_flush<IT, OC0, NOC>(out, dprev, hl);
            dprev = sdA.y;
        }
        tp_compute<IT, P0, P1, XA, XB, OC0, OC1, YA, YB>(Vr, xsA, yA, cA, out);
    }
    tp_flush<IT, OC0, NOC>(out, dprev, hl);
}

template <int IT, int P0, int P1, int XA, int XB, int OC0, int OC1, int YA, int YB,
          int MINB>
__global__ void __launch_bounds__(256, MINB)
tp_kernel(const float* __restrict__ W, int E) {
    int warp = (blockIdx.x * blockDim.x + threadIdx.x) >> 5;
    int halfid = warp * 2 + ((threadIdx.x & 31) >> 4);
    int nhalves = gridDim.x * 16;
    tp_body<IT, P0, P1, XA, XB, OC0, OC1, YA, YB>(W, E, halfid, nhalves);
}

// ============================================================================
// node MLP kernels (fused re-zero of message buffers)
// ============================================================================
template <int IT>
__global__ void node_kernel(const float* __restrict__ K1, const float* __restrict__ b1,
                            const float* __restrict__ K2, const float* __restrict__ b2,
                            float* __restrict__ outp, int N) {
    int lane = threadIdx.x & 31;
    int n = (blockIdx.x * blockDim.x + threadIdx.x) >> 5;
    if (n >= N) return;
    constexpr int D = (IT == 2) ? 1 : 9;

    float xo[D], t[D];
    if constexpr (IT == 0) {
        xo[0] = g_x[(n * 9) * FT + lane];
        t[0] = g_y[(n * 9) * FT + lane] + xo[0];
#pragma unroll
        for (int c = 1; c < 9; ++c) t[c] = g_y[(n * 9 + c) * FT + lane];
#pragma unroll
        for (int c = 0; c < 9; ++c) g_y[(n * 9 + c) * FT + lane] = 0.0f;
    } else if constexpr (IT == 1) {
#pragma unroll
        for (int c = 0; c < 9; ++c) {
            xo[c] = g_x[(n * 9 + c) * FT + lane];
            t[c] = xo[c] + g_y[(n * 9 + c) * FT + lane];
            g_y[(n * 9 + c) * FT + lane] = 0.0f;
        }
        g_y2[n * FT + lane] = 0.0f;
    } else {
        xo[0] = g_x[(n * 9) * FT + lane];
        t[0] = xo[0] + g_y2[n * FT + lane];
    }

    float u[D];
#pragma unroll
    for (int c = 0; c < D; ++c) u[c] = (c == 0) ? b1[lane] : 0.0f;
#pragma unroll
    for (int f2 = 0; f2 < 32; ++f2) {
        float kv = K1[f2 * FT + lane];
#pragma unroll
        for (int c = 0; c < D; ++c) {
            float tv = __shfl_sync(0xffffffffu, t[c], f2);
            u[c] += tv * kv;
        }
    }

    float sgt = u[0];
    float sig = 1.0f / (1.0f + expf(-sgt));
    float v[D];
    v[0] = sgt * sig;
#pragma unroll
    for (int c = 1; c < D; ++c) v[c] = u[c] * sig;

    float y2[D];
#pragma unroll
    for (int c = 0; c < D; ++c) y2[c] = (c == 0) ? b2[lane] : 0.0f;
#pragma unroll
    for (int f2 = 0; f2 < 32; ++f2) {
        float kv = K2[f2 * FT + lane];
#pragma unroll
        for (int c = 0; c < D; ++c) {
            float vv = __shfl_sync(0xffffffffu, v[c], f2);
            y2[c] += vv * kv;
        }
    }

    if constexpr (IT == 0) {
        g_x[(n * 9) * FT + lane] = xo[0] + y2[0];
#pragma unroll
        for (int c = 1; c < 9; ++c) g_x[(n * 9 + c) * FT + lane] = y2[c];
    } else if constexpr (IT == 1) {
#pragma unroll
        for (int c = 0; c < 9; ++c) g_x[(n * 9 + c) * FT + lane] = xo[c] + y2[c];
    } else {
        outp[n * FT + lane] = xo[0] + y2[0];
    }
}

// ============================================================================
// launch — launch #4 is tp_kernel<0> (the ncu-profiled slot)
// ============================================================================
extern "C" void kernel_launch(void* const* d_in, const int* in_sizes, int n_in,
                              void* d_out, int out_size) {
    const float* dr    = (const float*)d_in[0];
    const int*   Z     = (const int*)d_in[1];
    const int*   nbr   = (const int*)d_in[2];
    const float* embed = (const float*)d_in[3];
    const float* w0    = (const float*)d_in[4];
    const float* w1    = (const float*)d_in[5];
    const float* w2    = (const float*)d_in[6];
    const float* k1    = (const float*)d_in[7];
    const float* b1    = (const float*)d_in[8];
    const float* k2    = (const float*)d_in[9];
    const float* b2    = (const float*)d_in[10];
    float* outp = (float*)d_out;

    int E = in_sizes[0] / 3;
    int N = in_sizes[1];

    hist_initx_kernel<<<(E + 255) / 256, 256>>>(nbr, Z, embed, E, N);
    scan_kernel<<<1, 1024>>>(N);
    scatter_geom_kernel<<<(E + 255) / 256, 256>>>(nbr, dr, E);

    const int TB2 = 296;  // 2 blocks/SM
    const int TB3 = 444;  // 3 blocks/SM
    int nw_blocks = (N * 32 + 255) / 256;

    // iteration 0 (launch #4 — profiled)
    tp_kernel<0, 0, 3, 0, 1, 0, 9, 0, 9, 2><<<TB2, 256>>>(w0, E);
    node_kernel<0><<<nw_blocks, 256>>>(k1, b1, k2, b2, nullptr, N);

    // iteration 1: 6 pair-ILP kernels (NPL=3 for l1<=1, NPL=2 for l1=2)
    tp_kernel<1, 0,  3,  0, 1, 0, 9, 0, 9, 2><<<TB2, 256>>>(w1, E);  // (0,0,0)(0,1,1)(0,2,2)
    tp_kernel<1, 3,  6,  1, 4, 0, 4, 0, 4, 2><<<TB2, 256>>>(w1, E);  // (1,0,1)(1,1,0)(1,1,1)
    tp_kernel<1, 6,  9,  1, 4, 1, 9, 1, 9, 2><<<TB2, 256>>>(w1, E);  // (1,1,2)(1,2,1)(1,2,2)
    tp_kernel<1, 9,  11, 4, 9, 1, 9, 0, 4, 2><<<TB2, 256>>>(w1, E);  // (2,0,2)(2,1,1)
    tp_kernel<1, 11, 13, 4, 9, 0, 9, 1, 9, 2><<<TB2, 256>>>(w1, E);  // (2,1,2)(2,2,0)
    tp_kernel<1, 13, 15, 4, 9, 1, 9, 4, 9, 2><<<TB2, 256>>>(w1, E);  // (2,2,1)(2,2,2)
    node_kernel<1><<<nw_blocks, 256>>>(k1 + 1024, b1 + 32, k2 + 1024, b2 + 32, nullptr, N);

    // iteration 2: 3 single-path kernels at 3 blocks/SM
    tp_kernel<2, 0, 1, 0, 1, 0, 1, 0, 1, 3><<<TB3, 256>>>(w2, E);
    tp_kernel<2, 1, 2, 1, 4, 0, 1, 1, 4, 3><<<TB3, 256>>>(w2, E);
    tp_kernel<2, 2, 3, 4, 9, 0, 1, 4, 9, 3><<<TB3, 256>>>(w2, E);
    node_kernel<2><<<nw_blocks, 256>>>(k1 + 2048, b1 + 64, k2 + 2048, b2 + 64, outp, N);
}

// round 12
// speedup vs baseline: 1.0373x; 1.0373x over previous
#include <cuda_runtime.h>
#include <math.h>

// ============================================================================
// Compile-time real Clebsch-Gordan tensor (exact replica of reference _real_cg)
// ============================================================================
#define DH __host__ __device__

namespace cgct {

DH constexpr double fact(int n) {
    double r = 1.0;
    for (int i = 2; i <= n; ++i) r *= (double)i;
    return r;
}

DH constexpr double csqrt(double x) {
    if (x <= 0.0) return 0.0;
    double g = x < 1.0 ? 1.0 : x;
    for (int i = 0; i < 200; ++i) g = 0.5 * (g + x / g);
    return g;
}

DH constexpr int iabs(int x) { return x < 0 ? -x : x; }
DH constexpr double m1p(int k) { return (k % 2 != 0) ? -1.0 : 1.0; }

DH constexpr double clebsch(int j1, int m1, int j2, int m2, int j3, int m3) {
    if (m1 + m2 != m3) return 0.0;
    if (j3 < iabs(j1 - j2) || j3 > j1 + j2) return 0.0;
    double pre = csqrt((2.0 * j3 + 1.0) * fact(j1 + j2 - j3) * fact(j1 - j2 + j3) *
                       fact(-j1 + j2 + j3) / fact(j1 + j2 + j3 + 1));
    pre = pre * csqrt(fact(j3 + m3) * fact(j3 - m3) * fact(j1 - m1) *
                      fact(j1 + m1) * fact(j2 - m2) * fact(j2 + m2));
    double s = 0.0;
    for (int k = 0; k <= j1 + j2 + j3; ++k) {
        int d0 = k, d1 = j1 + j2 - j3 - k, d2 = j1 - m1 - k;
        int d3 = j2 + m2 - k, d4 = j3 - j2 + m1 + k, d5 = j3 - j1 - m2 + k;
        if (d0 < 0 || d1 < 0 || d2 < 0 || d3 < 0 || d4 < 0 || d5 < 0) continue;
        s += m1p(k) / (fact(d0) * fact(d1) * fact(d2) * fact(d3) * fact(d4) * fact(d5));
    }
    return pre * s;
}

struct C2 { double re, im; };
DH constexpr C2 cmul(C2 a, C2 b) { return {a.re * b.re - a.im * b.im, a.re * b.im + a.im * b.re}; }
DH constexpr C2 cconj(C2 a) { return {a.re, -a.im}; }

DH constexpr C2 Uel(int l, int i, int k) {
    double s2 = 1.0 / csqrt(2.0);
    int m = i - l;
    if (m == 0) return (k == l) ? C2{1.0, 0.0} : C2{0.0, 0.0};
    if (m > 0) {
        if (k == l + m) return C2{m1p(m) * s2, 0.0};
        if (k == l - m) return C2{s2, 0.0};
        return C2{0.0, 0.0};
    }
    if (k == l + m) return C2{0.0, s2};
    if (k == l - m) return C2{0.0, -m1p(m) * s2};
    return C2{0.0, 0.0};
}

DH constexpr int l_of(int I) { return I == 0 ? 0 : (I < 4 ? 1 : 2); }
DH constexpr int o_of(int l) { return l == 0 ? 0 : (l == 1 ? 1 : 4); }

DH constexpr double CGC(int I, int J, int K) {
    int l1 = l_of(I), l2 = l_of(J), l3 = l_of(K);
    if (l3 < iabs(l1 - l2) || l3 > l1 + l2) return 0.0;
    int i = I - o_of(l1), j = J - o_of(l2), kk = K - o_of(l3);
    double re = 0.0, im = 0.0;
    for (int a = 0; a < 2 * l1 + 1; ++a) {
        for (int b = 0; b < 2 * l2 + 1; ++b) {
            int m1 = a - l1, m2 = b - l2, m3 = m1 + m2;
            if (m3 < -l3 || m3 > l3) continue;
            int c = m3 + l3;
            double v = clebsch(l1, m1, l2, m2, l3, m3);
            if (v == 0.0) continue;
            C2 t = cmul(cmul(Uel(l1, i, a), Uel(l2, j, b)), cconj(Uel(l3, kk, c)));
            re += t.re * v;
            im += t.im * v;
        }
    }
    return re + im;
}

DH constexpr bool anyNZ(int I, int J, int o3, int nl3) {
    for (int c = 0; c < nl3; ++c)
        if (CGC(I, J, o3 + c) != 0.0) return true;
    return false;
}

} // namespace cgct

// ============================================================================
// Chebyshev U monomial coefficients: sin((k+1)a) = U_k(cos a) * sin(a)
// ============================================================================
struct ChebT {
    double T[8][8];
    constexpr ChebT() : T{} {
        T[0][0] = 1.0;
        T[1][1] = 2.0;
        for (int k = 2; k < 8; ++k)
            for (int j = 0; j < 8; ++j)
                T[k][j] = 2.0 * (j > 0 ? T[k - 1][j - 1] : 0.0) - T[k - 2][j];
    }
};
constexpr ChebT CT{};

// ============================================================================
// static-for
// ============================================================================
template <int I> struct IC { static constexpr int v = I; };
template <int N, class F>
__device__ __forceinline__ void sfor(F&& f) {
    if constexpr (N > 0) {
        sfor<N - 1>(f);
        f(IC<N - 1>{});
    }
}

template <int I>
__device__ __forceinline__ float getf4(const float4& v) {
    if constexpr (I == 0) return v.x;
    else if constexpr (I == 1) return v.y;
    else if constexpr (I == 2) return v.z;
    else return v.w;
}

// ============================================================================
// packed f32x2 helpers
// ============================================================================
using u64 = unsigned long long;

__device__ __forceinline__ u64 pk2(float lo, float hi) {
    u64 r;
    asm("mov.b64 %0, {%1, %2};" : "=l"(r) : "f"(lo), "f"(hi));
    return r;
}
__device__ __forceinline__ u64 pk1(float v) { return pk2(v, v); }
__device__ __forceinline__ void upk(u64 v, float& lo, float& hi) {
    asm("mov.b64 {%0, %1}, %2;" : "=f"(lo), "=f"(hi) : "l"(v));
}
__device__ __forceinline__ u64 f2mul(u64 a, u64 b) {
    u64 d;
    asm("mul.rn.f32x2 %0, %1, %2;" : "=l"(d) : "l"(a), "l"(b));
    return d;
}
__device__ __forceinline__ u64 f2fma(u64 a, u64 b, u64 c) {
    u64 d;
    asm("fma.rn.f32x2 %0, %1, %2, %3;" : "=l"(d) : "l"(a), "l"(b), "l"(c));
    return d;
}

// ============================================================================
// Problem constants & scratch
// ============================================================================
constexpr int NE = 320000;
constexpr int NN = 10000;
constexpr int NN_MAX = 10240;
constexpr int FT = 32;

__device__ float4 g_geom[NE * 3];
__device__ int2   g_sd[NE];         // (src, dst), sorted by dst
__device__ int    g_cnt[NN_MAX];    // zero at load; re-zeroed by scan each run
__device__ int    g_off[NN_MAX];
__device__ float  g_x[NN * 9 * FT];
__device__ float  g_y[NN * 9 * FT]; // zero at load; re-zeroed by node0/node1
__device__ float  g_y2[NN * FT];    // zero at load; re-zeroed by node1

// Path lists
template <int IT> struct PathsT;
template <> struct PathsT<0> {
    static constexpr int L[3][3] = {{0,0,0},{0,1,1},{0,2,2}};
};
template <> struct PathsT<1> {
    static constexpr int L[15][3] = {
        {0,0,0},{0,1,1},{0,2,2},
        {1,0,1},{1,1,0},{1,1,1},{1,1,2},{1,2,1},{1,2,2},
        {2,0,2},{2,1,1},{2,1,2},{2,2,0},{2,2,1},{2,2,2}};
};
template <> struct PathsT<2> {
    static constexpr int L[3][3] = {{0,0,0},{1,1,0},{2,2,0}};
};

// ============================================================================
// Launch 1: histogram (dst counts) + init node features
// ============================================================================
__global__ void hist_initx_kernel(const int* __restrict__ nbr,
                                  const int* __restrict__ Z,
                                  const float* __restrict__ embed,
                                  int E, int N) {
    int i = blockIdx.x * blockDim.x + threadIdx.x;
    if (i < E) atomicAdd(&g_cnt[nbr[i]], 1);
    if (i < N * FT) {
        int n = i >> 5, f = i & 31;
        g_x[(n * 9) * FT + f] = embed[Z[n] * FT + f];
    }
}

// ============================================================================
// Launch 2: exclusive scan of counts -> offsets; re-zero counts for next run
// ============================================================================
__global__ void scan_kernel(int N) {
    __shared__ int ps[1024];
    int tid = threadIdx.x;
    const int PER = 10;
    int base = tid * PER;
    int loc[PER];
    int s = 0;
#pragma unroll
    for (int i = 0; i < PER; ++i) {
        int idx = base + i;
        int v = 0;
        if (idx < N) {
            v = g_cnt[idx];
            g_cnt[idx] = 0;
        }
        loc[i] = s;
        s += v;
    }
    ps[tid] = s;
    __syncthreads();
    for (int off = 1; off < 1024; off <<= 1) {
        int v = (tid >= off) ? ps[tid - off] : 0;
        __syncthreads();
        ps[tid] += v;
        __syncthreads();
    }
    int pre = (tid > 0) ? ps[tid - 1] : 0;
#pragma unroll
    for (int i = 0; i < PER; ++i) {
        int idx = base + i;
        if (idx < N) g_off[idx] = pre + loc[i];
    }
}

// ============================================================================
// Launch 3: scatter edges into dst-sorted order + compute geometry
// ============================================================================
__global__ void scatter_geom_kernel(const int* __restrict__ nbr,
                                    const float* __restrict__ dr, int E) {
    int e = blockIdx.x * blockDim.x + threadIdx.x;
    if (e >= E) return;
    int d = nbr[e];
    int src = nbr[E + e];
    int pos = atomicAdd(&g_off[d], 1);
    g_sd[pos] = make_int2(src, d);

    float dx = dr[e * 3 + 0], dy = dr[e * 3 + 1], dz = dr[e * 3 + 2];
    float r2 = dx * dx + dy * dy + dz * dz + 1e-12f;
    float r = sqrtf(r2);
    float inv = 1.0f / r;
    float ux = dx * inv, uy = dy * inv, uz = dz * inv;

    float t = r * (1.0f / 6.0f);
    t = fminf(fmaxf(t, 0.0f), 1.0f - 1e-6f);
    float cut = (r < 6.0f) ? expf(1.0f - 1.0f / (1.0f - t * t)) : 0.0f;
    float cm = cut * ((d != src) ? 1.0f : 0.0f);

    const float pre = 0.5773502691896258f;   // sqrt(2/6)
    float arg = 0.5235987755982988f * r;     // pi*r/6
    float s1, c1;
    sincosf(arg, &s1, &c1);
    float ss1 = pre * inv * cm * s1;

    const float c0 = 0.28209479177387814f, c1y = 0.4886025119029199f;
    const float c2a = 1.0925484305920792f, c2b = 0.31539156525252005f,
                c2c = 0.5462742152960396f;
    float4* gg = &g_geom[pos * 3];
    gg[0] = make_float4(c0 * ss1, c1y * uy * ss1, c1y * uz * ss1, c1y * ux * ss1);
    gg[1] = make_float4(c2a * ux * uy * ss1, c2a * uy * uz * ss1,
                        c2b * (3.0f * uz * uz - 1.0f) * ss1, c2a * ux * uz * ss1);
    gg[2] = make_float4(c2c * (ux * ux - uy * uy) * ss1, c1, 0.0f, 0.0f);
}

// ============================================================================
// Geometry loader: only Y[YA..YB) plus cos(arg)
// ============================================================================
template <int YA, int YB>
__device__ __forceinline__ void load_geo(int e, float* y, float& c) {
    const float4* gg = &g_geom[e * 3];
    float4 A, B;
    if constexpr (YA < 4) A = gg[0];
    if constexpr (YB > 4 && YA < 8) B = gg[1];
    float2 C2v = *(const float2*)&gg[2];   // (Y8, cos)
    sfor<YB - YA>([&](auto II) {
        constexpr int ii = decltype(II)::v;
        constexpr int i = ii + YA;
        if constexpr (i < 4) y[ii] = getf4<i>(A);
        else if constexpr (i < 8) y[ii] = getf4<i - 4>(B);
        else y[ii] = C2v.x;
    });
    c = C2v.y;
}

// ============================================================================
// flush helper
// ============================================================================
template <int IT, int OC0, int NOC>
__device__ __forceinline__ void tp_flush(u64 (&out)[NOC], int d, int hl) {
#pragma unroll
    for (int c = 0; c < NOC; ++c) {
        float lo, hi;
        upk(out[c], lo, hi);
        float2* addr;
        if constexpr (IT == 2)
            addr = (float2*)&g_y2[d * FT + 2 * hl];
        else
            addr = (float2*)&g_y[(d * 9 + OC0 + c) * FT + 2 * hl];
        atomicAdd(addr, make_float2(lo, hi));
        out[c] = 0;
    }
}

// ============================================================================
// Single-edge compute: Horner radial weight + CG contraction into out.
// ============================================================================
template <int IT, int P0, int P1, int XA, int XB, int OC0, int OC1, int YA, int YB>
__device__ __forceinline__ void tp_compute(
    const u64 (&Vr)[(P1 - P0) * 8],
    const u64 (&xs)[XB - XA],
    const float (&y)[YB - YA], float cv,
    u64 (&out)[OC1 - OC0])
{
    using PT = PathsT<IT>;
    constexpr int NPL = P1 - P0;
    u64 cp = pk1(cv);
    sfor<NPL>([&](auto PI) {
        constexpr int pp = decltype(PI)::v;
        constexpr int p = P0 + pp;
        constexpr int l1 = PT::L[p][0], l2 = PT::L[p][1], l3 = PT::L[p][2];
        constexpr int o1 = cgct::o_of(l1), o2 = cgct::o_of(l2), o3 = cgct::o_of(l3);

        u64 w = Vr[pp * 8 + 7];
#pragma unroll
        for (int j = 6; j >= 0; --j) w = f2fma(w, cp, Vr[pp * 8 + j]);

        constexpr bool wInY = (2 * l2 + 1) < (2 * l1 + 1);
        if constexpr (wInY) {
            u64 yw[2 * l2 + 1];
            sfor<2 * l2 + 1>([&](auto BI) {
                constexpr int b = decltype(BI)::v;
                yw[b] = f2mul(pk1(y[o2 + b - YA]), w);
            });
            sfor<2 * l1 + 1>([&](auto AI) {
                constexpr int a = decltype(AI)::v;
                sfor<2 * l2 + 1>([&](auto BI) {
                    constexpr int b = decltype(BI)::v;
                    if constexpr (cgct::anyNZ(o1 + a, o2 + b, o3, 2 * l3 + 1)) {
                        u64 xy = f2mul(xs[o1 + a - XA], yw[b]);
                        sfor<2 * l3 + 1>([&](auto CI) {
                            constexpr int c = decltype(CI)::v;
                            constexpr double cgv = cgct::CGC(o1 + a, o2 + b, o3 + c);
                            if constexpr (cgv != 0.0) {
                                constexpr int oc = ((IT == 2) ? 0 : (o3 + c)) - OC0;
                                out[oc] = f2fma(pk1((float)cgv), xy, out[oc]);
                            }
                        });
                    }
                });
            });
        } else {
            sfor<2 * l1 + 1>([&](auto AI) {
                constexpr int a = decltype(AI)::v;
                u64 xa = f2mul(xs[o1 + a - XA], w);
                sfor<2 * l2 + 1>([&](auto BI) {
                    constexpr int b = decltype(BI)::v;
                    if constexpr (cgct::anyNZ(o1 + a, o2 + b, o3, 2 * l3 + 1)) {
                        u64 xy = f2mul(xa, pk1(y[o2 + b - YA]));
                        sfor<2 * l3 + 1>([&](auto CI) {
                            constexpr int c = decltype(CI)::v;
                            constexpr double cgv = cgct::CGC(o1 + a, o2 + b, o3 + c);
                            if constexpr (cgv != 0.0) {
                                constexpr int oc = ((IT == 2) ? 0 : (o3 + c)) - OC0;
                                out[oc] = f2fma(pk1((float)cgv), xy, out[oc]);
                            }
                        });
                    }
                });
            });
        }
    });
}

// ============================================================================
// TP body: warp-half (16 lanes) owns a contiguous dst-sorted edge range.
// PAIR processing: two edges per iteration; when both share a dst (common
// case, mean run length ~32) their compute trees form one straight-line
// block -> 2x instruction-level parallelism on the dependency chains.
// ============================================================================
template <int IT, int P0, int P1, int XA, int XB, int OC0, int OC1, int YA, int YB>
__device__ __forceinline__ void tp_body(const float* __restrict__ W, int E,
                                        int halfid, int nhalves) {
    constexpr int NPL = P1 - P0;
    constexpr int NX = XB - XA;
    constexpr int NOC = OC1 - OC0;
    constexpr int NY = YB - YA;

    int lane = threadIdx.x & 31;
    int hl = lane & 15;

    // load raw radial weights, transform to monomial (Chebyshev-U) basis
    u64 Vr[NPL * 8];
    {
        u64 Wr[NPL * 8];
#pragma unroll
        for (int i = 0; i < NPL * 8; ++i)
            Wr[i] = *(const u64*)(W + (P0 * 8 + i) * FT + 2 * hl);
        sfor<NPL>([&](auto PI) {
            constexpr int pp = decltype(PI)::v;
            sfor<8>([&](auto JI) {
                constexpr int j = decltype(JI)::v;
                u64 acc = 0;
                sfor<8>([&](auto KI) {
                    constexpr int k = decltype(KI)::v;
                    constexpr double tkj = CT.T[k][j];
                    if constexpr (tkj != 0.0)
                        acc = f2fma(pk1((float)tkj), Wr[pp * 8 + k], acc);
                });
                Vr[pp * 8 + j] = acc;
            });
        });
    }

    int eph = (E + nhalves - 1) / nhalves;
    int start = halfid * eph;
    int end = start + eph;
    if (end > E) end = E;
    if (start >= end) return;

    u64 out[NOC];
#pragma unroll
    for (int c = 0; c < NOC; ++c) out[c] = 0;
    int dprev = -1;

    int last = end - 1;
    int e = start;
    int2 sdA = g_sd[e];
    int2 sdB = g_sd[(e + 1 <= last) ? e + 1 : last];

#pragma unroll 1
    for (; e + 1 < end; e += 2) {
        // prefetch sd for the next pair
        int2 sdA2 = g_sd[(e + 2 <= last) ? e + 2 : last];
        int2 sdB2 = g_sd[(e + 3 <= last) ? e + 3 : last];

        // issue all loads for this pair up front (high MLP)
        u64 xsA[NX], xsB[NX];
#pragma unroll
        for (int a = 0; a < NX; ++a) {
            xsA[a] = *(const u64*)(g_x + ((sdA.x * 9 + XA + a) * FT) + 2 * hl);
            xsB[a] = *(const u64*)(g_x + ((sdB.x * 9 + XA + a) * FT) + 2 * hl);
        }
        float yA[NY], yB[NY];
        float cA, cB;
        load_geo<YA, YB>(e, yA, cA);
        load_geo<YA, YB>(e + 1, yB, cB);

        if (sdA.y != dprev) {
            if (dprev >= 0) tp_flush<IT, OC0, NOC>(out, dprev, hl);
            dprev = sdA.y;
        }

        if (sdB.y == sdA.y) {
            // fast path: one straight-line block, two independent trees
            tp_compute<IT, P0, P1, XA, XB, OC0, OC1, YA, YB>(Vr, xsA, yA, cA, out);
            tp_compute<IT, P0, P1, XA, XB, OC0, OC1, YA, YB>(Vr, xsB, yB, cB, out);
        } else {
            // dst boundary inside the pair (rare)
            tp_compute<IT, P0, P1, XA, XB, OC0, OC1, YA, YB>(Vr, xsA, yA, cA, out);
            tp_flush<IT, OC0, NOC>(out, dprev, hl);
            dprev = sdB.y;
            tp_compute<IT, P0, P1, XA, XB, OC0, OC1, YA, YB>(Vr, xsB, yB, cB, out);
        }

        sdA = sdA2;
        sdB = sdB2;
    }

    if (e < end) {   // odd tail (sdA == g_sd[e] here)
        u64 xsA[NX];
#pragma unroll
        for (int a = 0; a < NX; ++a)
            xsA[a] = *(const u64*)(g_x + ((sdA.x * 9 + XA + a) * FT) + 2 * hl);
        float yA[NY];
        float cA;
        load_geo<YA, YB>(e, yA, cA);
        if (sdA.y != dprev) {
            if (dprev >= 0) tp_flush<IT, OC0, NOC>(out, dprev, hl);
            dprev = sdA.y;
        }
        tp_compute<IT, P0, P1, XA, XB, OC0, OC1, YA, YB>(Vr, xsA, yA, cA, out);
    }
    tp_flush<IT, OC0, NOC>(out, dprev, hl);
}

template <int IT, int P0, int P1, int XA, int XB, int OC0, int OC1, int YA, int YB,
          int MINB>
__global__ void __launch_bounds__(256, MINB)
tp_kernel(const float* __restrict__ W, int E) {
    int warp = (blockIdx.x * blockDim.x + threadIdx.x) >> 5;
    int halfid = warp * 2 + ((threadIdx.x & 31) >> 4);
    int nhalves = gridDim.x * 16;
    tp_body<IT, P0, P1, XA, XB, OC0, OC1, YA, YB>(W, E, halfid, nhalves);
}

// ============================================================================
// node MLP kernels (fused re-zero of message buffers)
// ============================================================================
template <int IT>
__global__ void node_kernel(const float* __restrict__ K1, const float* __restrict__ b1,
                            const float* __restrict__ K2, const float* __restrict__ b2,
                            float* __restrict__ outp, int N) {
    int lane = threadIdx.x & 31;
    int n = (blockIdx.x * blockDim.x + threadIdx.x) >> 5;
    if (n >= N) return;
    constexpr int D = (IT == 2) ? 1 : 9;

    float xo[D], t[D];
    if constexpr (IT == 0) {
        xo[0] = g_x[(n * 9) * FT + lane];
        t[0] = g_y[(n * 9) * FT + lane] + xo[0];
#pragma unroll
        for (int c = 1; c < 9; ++c) t[c] = g_y[(n * 9 + c) * FT + lane];
#pragma unroll
        for (int c = 0; c < 9; ++c) g_y[(n * 9 + c) * FT + lane] = 0.0f;
    } else if constexpr (IT == 1) {
#pragma unroll
        for (int c = 0; c < 9; ++c) {
            xo[c] = g_x[(n * 9 + c) * FT + lane];
            t[c] = xo[c] + g_y[(n * 9 + c) * FT + lane];
            g_y[(n * 9 + c) * FT + lane] = 0.0f;
        }
        g_y2[n * FT + lane] = 0.0f;
    } else {
        xo[0] = g_x[(n * 9) * FT + lane];
        t[0] = xo[0] + g_y2[n * FT + lane];
    }

    float u[D];
#pragma unroll
    for (int c = 0; c < D; ++c) u[c] = (c == 0) ? b1[lane] : 0.0f;
#pragma unroll
    for (int f2 = 0; f2 < 32; ++f2) {
        float kv = K1[f2 * FT + lane];
#pragma unroll
        for (int c = 0; c < D; ++c) {
            float tv = __shfl_sync(0xffffffffu, t[c], f2);
            u[c] += tv * kv;
        }
    }

    float sgt = u[0];
    float sig = 1.0f / (1.0f + expf(-sgt));
    float v[D];
    v[0] = sgt * sig;
#pragma unroll
    for (int c = 1; c < D; ++c) v[c] = u[c] * sig;

    float y2[D];
#pragma unroll
    for (int c = 0; c < D; ++c) y2[c] = (c == 0) ? b2[lane] : 0.0f;
#pragma unroll
    for (int f2 = 0; f2 < 32; ++f2) {
        float kv = K2[f2 * FT + lane];
#pragma unroll
        for (int c = 0; c < D; ++c) {
            float vv = __shfl_sync(0xffffffffu, v[c], f2);
            y2[c] += vv * kv;
        }
    }

    if constexpr (IT == 0) {
        g_x[(n * 9) * FT + lane] = xo[0] + y2[0];
#pragma unroll
        for (int c = 1; c < 9; ++c) g_x[(n * 9 + c) * FT + lane] = y2[c];
    } else if constexpr (IT == 1) {
#pragma unroll
        for (int c = 0; c < 9; ++c) g_x[(n * 9 + c) * FT + lane] = xo[c] + y2[c];
    } else {
        outp[n * FT + lane] = xo[0] + y2[0];
    }
}

// ============================================================================
// launch — launch #4 is tp_kernel<0> (the ncu-profiled slot)
// ============================================================================
extern "C" void kernel_launch(void* const* d_in, const int* in_sizes, int n_in,
                              void* d_out, int out_size) {
    const float* dr    = (const float*)d_in[0];
    const int*   Z     = (const int*)d_in[1];
    const int*   nbr   = (const int*)d_in[2];
    const float* embed = (const float*)d_in[3];
    const float* w0    = (const float*)d_in[4];
    const float* w1    = (const float*)d_in[5];
    const float* w2    = (const float*)d_in[6];
    const float* k1    = (const float*)d_in[7];
    const float* b1    = (const float*)d_in[8];
    const float* k2    = (const float*)d_in[9];
    const float* b2    = (const float*)d_in[10];
    float* outp = (float*)d_out;

    int E = in_sizes[0] / 3;
    int N = in_sizes[1];

    hist_initx_kernel<<<(E + 255) / 256, 256>>>(nbr, Z, embed, E, N);
    scan_kernel<<<1, 1024>>>(N);
    scatter_geom_kernel<<<(E + 255) / 256, 256>>>(nbr, dr, E);

    const int TB2 = 296;  // 2 blocks/SM
    const int TB3 = 444;  // 3 blocks/SM
    int nw_blocks = (N * 32 + 255) / 256;

    // iteration 0 (launch #4 — profiled)
    tp_kernel<0, 0, 3, 0, 1, 0, 9, 0, 9, 2><<<TB2, 256>>>(w0, E);
    node_kernel<0><<<nw_blocks, 256>>>(k1, b1, k2, b2, nullptr, N);

    // iteration 1: 5 pair-ILP kernels, NPL=3 each (no extra edge passes)
    tp_kernel<1, 0,  3,  0, 1, 0, 9, 0, 9, 2><<<TB2, 256>>>(w1, E);  // l1=0 paths
    tp_kernel<1, 3,  6,  1, 4, 0, 4, 0, 4, 2><<<TB2, 256>>>(w1, E);  // (1,0,1)(1,1,0)(1,1,1)
    tp_kernel<1, 6,  9,  1, 4, 1, 9, 1, 9, 2><<<TB2, 256>>>(w1, E);  // (1,1,2)(1,2,1)(1,2,2)
    tp_kernel<1, 9,  12, 4, 9, 1, 9, 0, 4, 2><<<TB2, 256>>>(w1, E);  // (2,0,2)(2,1,1)(2,1,2)
    tp_kernel<1, 12, 15, 4, 9, 0, 9, 4, 9, 2><<<TB2, 256>>>(w1, E);  // (2,2,0)(2,2,1)(2,2,2)
    node_kernel<1><<<nw_blocks, 256>>>(k1 + 1024, b1 + 32, k2 + 1024, b2 + 32, nullptr, N);

    // iteration 2: 3 single-path kernels at 3 blocks/SM (disjoint x/Y slices)
    tp_kernel<2, 0, 1, 0, 1, 0, 1, 0, 1, 3><<<TB3, 256>>>(w2, E);
    tp_kernel<2, 1, 2, 1, 4, 0, 1, 1, 4, 3><<<TB3, 256>>>(w2, E);
    tp_kernel<2, 2, 3, 4, 9, 0, 1, 4, 9, 3><<<TB3, 256>>>(w2, E);
    node_kernel<2><<<nw_blocks, 256>>>(k1 + 2048, b1 + 64, k2 + 2048, b2 + 64, outp, N);
}

// round 13
// speedup vs baseline: 1.0778x; 1.0391x over previous
#include <cuda_runtime.h>
#include <math.h>

// ============================================================================
// Compile-time real Clebsch-Gordan tensor (exact replica of reference _real_cg)
// ============================================================================
#define DH __host__ __device__

namespace cgct {

DH constexpr double fact(int n) {
    double r = 1.0;
    for (int i = 2; i <= n; ++i) r *= (double)i;
    return r;
}

DH constexpr double csqrt(double x) {
    if (x <= 0.0) return 0.0;
    double g = x < 1.0 ? 1.0 : x;
    for (int i = 0; i < 200; ++i) g = 0.5 * (g + x / g);
    return g;
}

DH constexpr int iabs(int x) { return x < 0 ? -x : x; }
DH constexpr double m1p(int k) { return (k % 2 != 0) ? -1.0 : 1.0; }

DH constexpr double clebsch(int j1, int m1, int j2, int m2, int j3, int m3) {
    if (m1 + m2 != m3) return 0.0;
    if (j3 < iabs(j1 - j2) || j3 > j1 + j2) return 0.0;
    double pre = csqrt((2.0 * j3 + 1.0) * fact(j1 + j2 - j3) * fact(j1 - j2 + j3) *
                       fact(-j1 + j2 + j3) / fact(j1 + j2 + j3 + 1));
    pre = pre * csqrt(fact(j3 + m3) * fact(j3 - m3) * fact(j1 - m1) *
                      fact(j1 + m1) * fact(j2 - m2) * fact(j2 + m2));
    double s = 0.0;
    for (int k = 0; k <= j1 + j2 + j3; ++k) {
        int d0 = k, d1 = j1 + j2 - j3 - k, d2 = j1 - m1 - k;
        int d3 = j2 + m2 - k, d4 = j3 - j2 + m1 + k, d5 = j3 - j1 - m2 + k;
        if (d0 < 0 || d1 < 0 || d2 < 0 || d3 < 0 || d4 < 0 || d5 < 0) continue;
        s += m1p(k) / (fact(d0) * fact(d1) * fact(d2) * fact(d3) * fact(d4) * fact(d5));
    }
    return pre * s;
}

struct C2 { double re, im; };
DH constexpr C2 cmul(C2 a, C2 b) { return {a.re * b.re - a.im * b.im, a.re * b.im + a.im * b.re}; }
DH constexpr C2 cconj(C2 a) { return {a.re, -a.im}; }

DH constexpr C2 Uel(int l, int i, int k) {
    double s2 = 1.0 / csqrt(2.0);
    int m = i - l;
    if (m == 0) return (k == l) ? C2{1.0, 0.0} : C2{0.0, 0.0};
    if (m > 0) {
        if (k == l + m) return C2{m1p(m) * s2, 0.0};
        if (k == l - m) return C2{s2, 0.0};
        return C2{0.0, 0.0};
    }
    if (k == l + m) return C2{0.0, s2};
    if (k == l - m) return C2{0.0, -m1p(m) * s2};
    return C2{0.0, 0.0};
}

DH constexpr int l_of(int I) { return I == 0 ? 0 : (I < 4 ? 1 : 2); }
DH constexpr int o_of(int l) { return l == 0 ? 0 : (l == 1 ? 1 : 4); }

DH constexpr double CGC(int I, int J, int K) {
    int l1 = l_of(I), l2 = l_of(J), l3 = l_of(K);
    if (l3 < iabs(l1 - l2) || l3 > l1 + l2) return 0.0;
    int i = I - o_of(l1), j = J - o_of(l2), kk = K - o_of(l3);
    double re = 0.0, im = 0.0;
    for (int a = 0; a < 2 * l1 + 1; ++a) {
        for (int b = 0; b < 2 * l2 + 1; ++b) {
            int m1 = a - l1, m2 = b - l2, m3 = m1 + m2;
            if (m3 < -l3 || m3 > l3) continue;
            int c = m3 + l3;
            double v = clebsch(l1, m1, l2, m2, l3, m3);
            if (v == 0.0) continue;
            C2 t = cmul(cmul(Uel(l1, i, a), Uel(l2, j, b)), cconj(Uel(l3, kk, c)));
            re += t.re * v;
            im += t.im * v;
        }
    }
    return re + im;
}

DH constexpr bool anyNZ(int I, int J, int o3, int nl3) {
    for (int c = 0; c < nl3; ++c)
        if (CGC(I, J, o3 + c) != 0.0) return true;
    return false;
}

} // namespace cgct

// ============================================================================
// Chebyshev U monomial coefficients: sin((k+1)a) = U_k(cos a) * sin(a)
// ============================================================================
struct ChebT {
    double T[8][8];
    constexpr ChebT() : T{} {
        T[0][0] = 1.0;
        T[1][1] = 2.0;
        for (int k = 2; k < 8; ++k)
            for (int j = 0; j < 8; ++j)
                T[k][j] = 2.0 * (j > 0 ? T[k - 1][j - 1] : 0.0) - T[k - 2][j];
    }
};
constexpr ChebT CT{};

// ============================================================================
// static-for
// ============================================================================
template <int I> struct IC { static constexpr int v = I; };
template <int N, class F>
__device__ __forceinline__ void sfor(F&& f) {
    if constexpr (N > 0) {
        sfor<N - 1>(f);
        f(IC<N - 1>{});
    }
}

template <int I>
__device__ __forceinline__ float getf4(const float4& v) {
    if constexpr (I == 0) return v.x;
    else if constexpr (I == 1) return v.y;
    else if constexpr (I == 2) return v.z;
    else return v.w;
}

// ============================================================================
// packed f32x2 helpers
// ============================================================================
using u64 = unsigned long long;

__device__ __forceinline__ u64 pk2(float lo, float hi) {
    u64 r;
    asm("mov.b64 %0, {%1, %2};" : "=l"(r) : "f"(lo), "f"(hi));
    return r;
}
__device__ __forceinline__ u64 pk1(float v) { return pk2(v, v); }
__device__ __forceinline__ void upk(u64 v, float& lo, float& hi) {
    asm("mov.b64 {%0, %1}, %2;" : "=f"(lo), "=f"(hi) : "l"(v));
}
__device__ __forceinline__ u64 f2mul(u64 a, u64 b) {
    u64 d;
    asm("mul.rn.f32x2 %0, %1, %2;" : "=l"(d) : "l"(a), "l"(b));
    return d;
}
__device__ __forceinline__ u64 f2fma(u64 a, u64 b, u64 c) {
    u64 d;
    asm("fma.rn.f32x2 %0, %1, %2, %3;" : "=l"(d) : "l"(a), "l"(b), "l"(c));
    return d;
}

// ============================================================================
// Problem constants & scratch
// ============================================================================
constexpr int NE = 320000;
constexpr int NN = 10000;
constexpr int NN_MAX = 10240;
constexpr int FT = 32;

__device__ float4 g_geom[NE * 3];
__device__ int2   g_sd[NE];         // (src, dst), sorted by dst
__device__ int    g_cnt[NN_MAX];    // zero at load; re-zeroed by scan each run
__device__ int    g_off[NN_MAX];
__device__ float  g_x[NN * 9 * FT];
__device__ float  g_y[NN * 9 * FT]; // zero at load; re-zeroed by node0/node1
__device__ float  g_y2[NN * FT];    // zero at load; re-zeroed by node1

// Path lists
template <int IT> struct PathsT;
template <> struct PathsT<0> {
    static constexpr int L[3][3] = {{0,0,0},{0,1,1},{0,2,2}};
};
template <> struct PathsT<1> {
    static constexpr int L[15][3] = {
        {0,0,0},{0,1,1},{0,2,2},
        {1,0,1},{1,1,0},{1,1,1},{1,1,2},{1,2,1},{1,2,2},
        {2,0,2},{2,1,1},{2,1,2},{2,2,0},{2,2,1},{2,2,2}};
};
template <> struct PathsT<2> {
    static constexpr int L[3][3] = {{0,0,0},{1,1,0},{2,2,0}};
};

// ============================================================================
// Launch 1: histogram (dst counts) + init node features
// ============================================================================
__global__ void hist_initx_kernel(const int* __restrict__ nbr,
                                  const int* __restrict__ Z,
                                  const float* __restrict__ embed,
                                  int E, int N) {
    int i = blockIdx.x * blockDim.x + threadIdx.x;
    if (i < E) atomicAdd(&g_cnt[nbr[i]], 1);
    if (i < N * FT) {
        int n = i >> 5, f = i & 31;
        g_x[(n * 9) * FT + f] = embed[Z[n] * FT + f];
    }
}

// ============================================================================
// Launch 2: exclusive scan of counts -> offsets; re-zero counts for next run
// ============================================================================
__global__ void scan_kernel(int N) {
    __shared__ int ps[1024];
    int tid = threadIdx.x;
    const int PER = 10;
    int base = tid * PER;
    int loc[PER];
    int s = 0;
#pragma unroll
    for (int i = 0; i < PER; ++i) {
        int idx = base + i;
        int v = 0;
        if (idx < N) {
            v = g_cnt[idx];
            g_cnt[idx] = 0;
        }
        loc[i] = s;
        s += v;
    }
    ps[tid] = s;
    __syncthreads();
    for (int off = 1; off < 1024; off <<= 1) {
        int v = (tid >= off) ? ps[tid - off] : 0;
        __syncthreads();
        ps[tid] += v;
        __syncthreads();
    }
    int pre = (tid > 0) ? ps[tid - 1] : 0;
#pragma unroll
    for (int i = 0; i < PER; ++i) {
        int idx = base + i;
        if (idx < N) g_off[idx] = pre + loc[i];
    }
}

// ============================================================================
// Launch 3: scatter edges into dst-sorted order + compute geometry
// ============================================================================
__global__ void scatter_geom_kernel(const int* __restrict__ nbr,
                                    const float* __restrict__ dr, int E) {
    int e = blockIdx.x * blockDim.x + threadIdx.x;
    if (e >= E) return;
    int d = nbr[e];
    int src = nbr[E + e];
    int pos = atomicAdd(&g_off[d], 1);
    g_sd[pos] = make_int2(src, d);

    float dx = dr[e * 3 + 0], dy = dr[e * 3 + 1], dz = dr[e * 3 + 2];
    float r2 = dx * dx + dy * dy + dz * dz + 1e-12f;
    float r = sqrtf(r2);
    float inv = 1.0f / r;
    float ux = dx * inv, uy = dy * inv, uz = dz * inv;

    float t = r * (1.0f / 6.0f);
    t = fminf(fmaxf(t, 0.0f), 1.0f - 1e-6f);
    float cut = (r < 6.0f) ? expf(1.0f - 1.0f / (1.0f - t * t)) : 0.0f;
    float cm = cut * ((d != src) ? 1.0f : 0.0f);

    const float pre = 0.5773502691896258f;   // sqrt(2/6)
    float arg = 0.5235987755982988f * r;     // pi*r/6
    float s1, c1;
    sincosf(arg, &s1, &c1);
    float ss1 = pre * inv * cm * s1;

    const float c0 = 0.28209479177387814f, c1y = 0.4886025119029199f;
    const float c2a = 1.0925484305920792f, c2b = 0.31539156525252005f,
                c2c = 0.5462742152960396f;
    float4* gg = &g_geom[pos * 3];
    gg[0] = make_float4(c0 * ss1, c1y * uy * ss1, c1y * uz * ss1, c1y * ux * ss1);
    gg[1] = make_float4(c2a * ux * uy * ss1, c2a * uy * uz * ss1,
                        c2b * (3.0f * uz * uz - 1.0f) * ss1, c2a * ux * uz * ss1);
    gg[2] = make_float4(c2c * (ux * ux - uy * uy) * ss1, c1, 0.0f, 0.0f);
}

// ============================================================================
// Geometry loader: only Y[YA..YB) plus cos(arg)
// ============================================================================
template <int YA, int YB>
__device__ __forceinline__ void load_geo(int e, float* y, float& c) {
    const float4* gg = &g_geom[e * 3];
    float4 A, B;
    if constexpr (YA < 4) A = gg[0];
    if constexpr (YB > 4 && YA < 8) B = gg[1];
    float2 C2v = *(const float2*)&gg[2];   // (Y8, cos)
    sfor<YB - YA>([&](auto II) {
        constexpr int ii = decltype(II)::v;
        constexpr int i = ii + YA;
        if constexpr (i < 4) y[ii] = getf4<i>(A);
        else if constexpr (i < 8) y[ii] = getf4<i - 4>(B);
        else y[ii] = C2v.x;
    });
    c = C2v.y;
}

// ============================================================================
// flush helper
// ============================================================================
template <int IT, int OC0, int NOC>
__device__ __forceinline__ void tp_flush(u64 (&out)[NOC], int d, int hl) {
#pragma unroll
    for (int c = 0; c < NOC; ++c) {
        float lo, hi;
        upk(out[c], lo, hi);
        float2* addr;
        if constexpr (IT == 2)
            addr = (float2*)&g_y2[d * FT + 2 * hl];
        else
            addr = (float2*)&g_y[(d * 9 + OC0 + c) * FT + 2 * hl];
        atomicAdd(addr, make_float2(lo, hi));
        out[c] = 0;
    }
}

// ============================================================================
// Single-edge compute: Horner radial weight + CG contraction into out.
// ============================================================================
template <int IT, int P0, int P1, int XA, int XB, int OC0, int OC1, int YA, int YB>
__device__ __forceinline__ void tp_compute(
    const u64 (&Vr)[(P1 - P0) * 8],
    const u64 (&xs)[XB - XA],
    const float (&y)[YB - YA], float cv,
    u64 (&out)[OC1 - OC0])
{
    using PT = PathsT<IT>;
    constexpr int NPL = P1 - P0;
    u64 cp = pk1(cv);
    sfor<NPL>([&](auto PI) {
        constexpr int pp = decltype(PI)::v;
        constexpr int p = P0 + pp;
        constexpr int l1 = PT::L[p][0], l2 = PT::L[p][1], l3 = PT::L[p][2];
        constexpr int o1 = cgct::o_of(l1), o2 = cgct::o_of(l2), o3 = cgct::o_of(l3);

        u64 w = Vr[pp * 8 + 7];
#pragma unroll
        for (int j = 6; j >= 0; --j) w = f2fma(w, cp, Vr[pp * 8 + j]);

        constexpr bool wInY = (2 * l2 + 1) < (2 * l1 + 1);
        if constexpr (wInY) {
            u64 yw[2 * l2 + 1];
            sfor<2 * l2 + 1>([&](auto BI) {
                constexpr int b = decltype(BI)::v;
                yw[b] = f2mul(pk1(y[o2 + b - YA]), w);
            });
            sfor<2 * l1 + 1>([&](auto AI) {
                constexpr int a = decltype(AI)::v;
                sfor<2 * l2 + 1>([&](auto BI) {
                    constexpr int b = decltype(BI)::v;
                    if constexpr (cgct::anyNZ(o1 + a, o2 + b, o3, 2 * l3 + 1)) {
                        u64 xy = f2mul(xs[o1 + a - XA], yw[b]);
                        sfor<2 * l3 + 1>([&](auto CI) {
                            constexpr int c = decltype(CI)::v;
                            constexpr double cgv = cgct::CGC(o1 + a, o2 + b, o3 + c);
                            if constexpr (cgv != 0.0) {
                                constexpr int oc = ((IT == 2) ? 0 : (o3 + c)) - OC0;
                                out[oc] = f2fma(pk1((float)cgv), xy, out[oc]);
                            }
                        });
                    }
                });
            });
        } else {
            sfor<2 * l1 + 1>([&](auto AI) {
                constexpr int a = decltype(AI)::v;
                u64 xa = f2mul(xs[o1 + a - XA], w);
                sfor<2 * l2 + 1>([&](auto BI) {
                    constexpr int b = decltype(BI)::v;
                    if constexpr (cgct::anyNZ(o1 + a, o2 + b, o3, 2 * l3 + 1)) {
                        u64 xy = f2mul(xa, pk1(y[o2 + b - YA]));
                        sfor<2 * l3 + 1>([&](auto CI) {
                            constexpr int c = decltype(CI)::v;
                            constexpr double cgv = cgct::CGC(o1 + a, o2 + b, o3 + c);
                            if constexpr (cgv != 0.0) {
                                constexpr int oc = ((IT == 2) ? 0 : (o3 + c)) - OC0;
                                out[oc] = f2fma(pk1((float)cgv), xy, out[oc]);
                            }
                        });
                    }
                });
            });
        }
    });
}

// ============================================================================
// TP body: warp-half (16 lanes) owns a contiguous dst-sorted edge range.
// PAIR processing (2x ILP). PREF=1: prefetch next pair's sd at loop top
// (R12 winner behavior). PREF=0: load sd at loop bottom (saves 4 registers,
// sd is sequential+uniform so L1-resident; used by register-tight kernels).
// ============================================================================
template <int IT, int P0, int P1, int XA, int XB, int OC0, int OC1, int YA, int YB,
          int PREF>
__device__ __forceinline__ void tp_body(const float* __restrict__ W, int E,
                                        int halfid, int nhalves) {
    constexpr int NPL = P1 - P0;
    constexpr int NX = XB - XA;
    constexpr int NOC = OC1 - OC0;
    constexpr int NY = YB - YA;

    int lane = threadIdx.x & 31;
    int hl = lane & 15;

    // load raw radial weights, transform to monomial (Chebyshev-U) basis
    u64 Vr[NPL * 8];
    {
        u64 Wr[NPL * 8];
#pragma unroll
        for (int i = 0; i < NPL * 8; ++i)
            Wr[i] = *(const u64*)(W + (P0 * 8 + i) * FT + 2 * hl);
        sfor<NPL>([&](auto PI) {
            constexpr int pp = decltype(PI)::v;
            sfor<8>([&](auto JI) {
                constexpr int j = decltype(JI)::v;
                u64 acc = 0;
                sfor<8>([&](auto KI) {
                    constexpr int k = decltype(KI)::v;
                    constexpr double tkj = CT.T[k][j];
                    if constexpr (tkj != 0.0)
                        acc = f2fma(pk1((float)tkj), Wr[pp * 8 + k], acc);
                });
                Vr[pp * 8 + j] = acc;
            });
        });
    }

    int eph = (E + nhalves - 1) / nhalves;
    int start = halfid * eph;
    int end = start + eph;
    if (end > E) end = E;
    if (start >= end) return;

    u64 out[NOC];
#pragma unroll
    for (int c = 0; c < NOC; ++c) out[c] = 0;
    int dprev = -1;

    int last = end - 1;
    int e = start;
    int2 sdA = g_sd[e];
    int2 sdB = g_sd[(e + 1 <= last) ? e + 1 : last];

#pragma unroll 1
    for (; e + 1 < end; e += 2) {
        int2 sdA2, sdB2;
        if constexpr (PREF) {
            sdA2 = g_sd[(e + 2 <= last) ? e + 2 : last];
            sdB2 = g_sd[(e + 3 <= last) ? e + 3 : last];
        }

        // issue all loads for this pair up front (high MLP)
        u64 xsA[NX], xsB[NX];
#pragma unroll
        for (int a = 0; a < NX; ++a) {
            xsA[a] = *(const u64*)(g_x + ((sdA.x * 9 + XA + a) * FT) + 2 * hl);
            xsB[a] = *(const u64*)(g_x + ((sdB.x * 9 + XA + a) * FT) + 2 * hl);
        }
        float yA[NY], yB[NY];
        float cA, cB;
        load_geo<YA, YB>(e, yA, cA);
        load_geo<YA, YB>(e + 1, yB, cB);

        if (sdA.y != dprev) {
            if (dprev >= 0) tp_flush<IT, OC0, NOC>(out, dprev, hl);
            dprev = sdA.y;
        }

        if (sdB.y == sdA.y) {
            // fast path: one straight-line block, two independent trees
            tp_compute<IT, P0, P1, XA, XB, OC0, OC1, YA, YB>(Vr, xsA, yA, cA, out);
            tp_compute<IT, P0, P1, XA, XB, OC0, OC1, YA, YB>(Vr, xsB, yB, cB, out);
        } else {
            // dst boundary inside the pair (rare)
            tp_compute<IT, P0, P1, XA, XB, OC0, OC1, YA, YB>(Vr, xsA, yA, cA, out);
            tp_flush<IT, OC0, NOC>(out, dprev, hl);
            dprev = sdB.y;
            tp_compute<IT, P0, P1, XA, XB, OC0, OC1, YA, YB>(Vr, xsB, yB, cB, out);
        }

        if constexpr (PREF) {
            sdA = sdA2;
            sdB = sdB2;
        } else {
            sdA = g_sd[(e + 2 <= last) ? e + 2 : last];
            sdB = g_sd[(e + 3 <= last) ? e + 3 : last];
        }
    }

    if (e < end) {   // odd tail (sdA == g_sd[e] here)
        u64 xsA[NX];
#pragma unroll
        for (int a = 0; a < NX; ++a)
            xsA[a] = *(const u64*)(g_x + ((sdA.x * 9 + XA + a) * FT) + 2 * hl);
        float yA[NY];
        float cA;
        load_geo<YA, YB>(e, yA, cA);
        if (sdA.y != dprev) {
            if (dprev >= 0) tp_flush<IT, OC0, NOC>(out, dprev, hl);
            dprev = sdA.y;
        }
        tp_compute<IT, P0, P1, XA, XB, OC0, OC1, YA, YB>(Vr, xsA, yA, cA, out);
    }
    tp_flush<IT, OC0, NOC>(out, dprev, hl);
}

template <int IT, int P0, int P1, int XA, int XB, int OC0, int OC1, int YA, int YB,
          int MINB, int PREF>
__global__ void __launch_bounds__(256, MINB)
tp_kernel(const float* __restrict__ W, int E) {
    int warp = (blockIdx.x * blockDim.x + threadIdx.x) >> 5;
    int halfid = warp * 2 + ((threadIdx.x & 31) >> 4);
    int nhalves = gridDim.x * 16;
    tp_body<IT, P0, P1, XA, XB, OC0, OC1, YA, YB, PREF>(W, E, halfid, nhalves);
}

// ============================================================================
// node MLP kernels (fused re-zero of message buffers)
// ============================================================================
template <int IT>
__global__ void node_kernel(const float* __restrict__ K1, const float* __restrict__ b1,
                            const float* __restrict__ K2, const float* __restrict__ b2,
                            float* __restrict__ outp, int N) {
    int lane = threadIdx.x & 31;
    int n = (blockIdx.x * blockDim.x + threadIdx.x) >> 5;
    if (n >= N) return;
    constexpr int D = (IT == 2) ? 1 : 9;

    float xo[D], t[D];
    if constexpr (IT == 0) {
        xo[0] = g_x[(n * 9) * FT + lane];
        t[0] = g_y[(n * 9) * FT + lane] + xo[0];
#pragma unroll
        for (int c = 1; c < 9; ++c) t[c] = g_y[(n * 9 + c) * FT + lane];
#pragma unroll
        for (int c = 0; c < 9; ++c) g_y[(n * 9 + c) * FT + lane] = 0.0f;
    } else if constexpr (IT == 1) {
#pragma unroll
        for (int c = 0; c < 9; ++c) {
            xo[c] = g_x[(n * 9 + c) * FT + lane];
            t[c] = xo[c] + g_y[(n * 9 + c) * FT + lane];
            g_y[(n * 9 + c) * FT + lane] = 0.0f;
        }
        g_y2[n * FT + lane] = 0.0f;
    } else {
        xo[0] = g_x[(n * 9) * FT + lane];
        t[0] = xo[0] + g_y2[n * FT + lane];
    }

    float u[D];
#pragma unroll
    for (int c = 0; c < D; ++c) u[c] = (c == 0) ? b1[lane] : 0.0f;
#pragma unroll
    for (int f2 = 0; f2 < 32; ++f2) {
        float kv = K1[f2 * FT + lane];
#pragma unroll
        for (int c = 0; c < D; ++c) {
            float tv = __shfl_sync(0xffffffffu, t[c], f2);
            u[c] += tv * kv;
        }
    }

    float sgt = u[0];
    float sig = 1.0f / (1.0f + expf(-sgt));
    float v[D];
    v[0] = sgt * sig;
#pragma unroll
    for (int c = 1; c < D; ++c) v[c] = u[c] * sig;

    float y2[D];
#pragma unroll
    for (int c = 0; c < D; ++c) y2[c] = (c == 0) ? b2[lane] : 0.0f;
#pragma unroll
    for (int f2 = 0; f2 < 32; ++f2) {
        float kv = K2[f2 * FT + lane];
#pragma unroll
        for (int c = 0; c < D; ++c) {
            float vv = __shfl_sync(0xffffffffu, v[c], f2);
            y2[c] += vv * kv;
        }
    }

    if constexpr (IT == 0) {
        g_x[(n * 9) * FT + lane] = xo[0] + y2[0];
#pragma unroll
        for (int c = 1; c < 9; ++c) g_x[(n * 9 + c) * FT + lane] = y2[c];
    } else if constexpr (IT == 1) {
#pragma unroll
        for (int c = 0; c < 9; ++c) g_x[(n * 9 + c) * FT + lane] = xo[c] + y2[c];
    } else {
        outp[n * FT + lane] = xo[0] + y2[0];
    }
}

// ============================================================================
// launch — launch #4 is tp_kernel<0> (the ncu-profiled slot)
// ============================================================================
extern "C" void kernel_launch(void* const* d_in, const int* in_sizes, int n_in,
                              void* d_out, int out_size) {
    const float* dr    = (const float*)d_in[0];
    const int*   Z     = (const int*)d_in[1];
    const int*   nbr   = (const int*)d_in[2];
    const float* embed = (const float*)d_in[3];
    const float* w0    = (const float*)d_in[4];
    const float* w1    = (const float*)d_in[5];
    const float* w2    = (const float*)d_in[6];
    const float* k1    = (const float*)d_in[7];
    const float* b1    = (const float*)d_in[8];
    const float* k2    = (const float*)d_in[9];
    const float* b2    = (const float*)d_in[10];
    float* outp = (float*)d_out;

    int E = in_sizes[0] / 3;
    int N = in_sizes[1];

    hist_initx_kernel<<<(E + 255) / 256, 256>>>(nbr, Z, embed, E, N);
    scan_kernel<<<1, 1024>>>(N);
    scatter_geom_kernel<<<(E + 255) / 256, 256>>>(nbr, dr, E);

    const int TB2 = 296;  // 2 blocks/SM
    int nw_blocks = (N * 32 + 255) / 256;

    // iteration 0 (launch #4 — profiled)
    tp_kernel<0, 0, 3, 0, 1, 0, 9, 0, 9, 2, 1><<<TB2, 256>>>(w0, E);
    node_kernel<0><<<nw_blocks, 256>>>(k1, b1, k2, b2, nullptr, N);

    // iteration 1: 5 pair-ILP kernels, NPL=3 each (no extra edge passes)
    tp_kernel<1, 0,  3,  0, 1, 0, 9, 0, 9, 2, 1><<<TB2, 256>>>(w1, E);  // l1=0 paths
    tp_kernel<1, 3,  6,  1, 4, 0, 4, 0, 4, 2, 1><<<TB2, 256>>>(w1, E);  // (1,0,1)(1,1,0)(1,1,1)
    tp_kernel<1, 6,  9,  1, 4, 1, 9, 1, 9, 2, 1><<<TB2, 256>>>(w1, E);  // (1,1,2)(1,2,1)(1,2,2)
    tp_kernel<1, 9,  12, 4, 9, 1, 9, 0, 4, 2, 1><<<TB2, 256>>>(w1, E);  // (2,0,2)(2,1,1)(2,1,2)
    tp_kernel<1, 12, 15, 4, 9, 0, 9, 4, 9, 2, 1><<<TB2, 256>>>(w1, E);  // (2,2,0)(2,2,1)(2,2,2)
    node_kernel<1><<<nw_blocks, 256>>>(k1 + 1024, b1 + 32, k2 + 1024, b2 + 32, nullptr, N);

    // iteration 2: ONE merged pair-ILP kernel (all 3 paths, one edge pass;
    // PREF=0 to fit the register budget)
    tp_kernel<2, 0, 3, 0, 9, 0, 1, 0, 9, 2, 0><<<TB2, 256>>>(w2, E);
    node_kernel<2><<<nw_blocks, 256>>>(k1 + 2048, b1 + 64, k2 + 2048, b2 + 64, outp, N);
}